// round 2
// baseline (speedup 1.0000x reference)
#include <cuda_runtime.h>
#include <cuda_bf16.h>
#include <math.h>

// Problem constants
#define BSZ   16
#define TLEN  512
#define IDIM  8
#define HDIM  256
#define NPAIR 32896              // H*(H+1)/2
#define KSLICE 224               // pairs per CTA (mult of 16)
#define NCTA  148
#define PPAD  (NCTA*KSLICE)      // 33152 padded pairs
#define ASTRIDE 232              // bf16 elems per A row (116 words -> conflict-free)
#define PSTRIDE 232
#define NOISE_STD 0.05f
#define TAUC 0.2f

#define OFFJ(j) ((j)*HDIM - ((j)*((j)-1))/2)

// Scratch (static device globals: no allocation allowed)
__device__ __nv_bfloat16 g_ws[256 * PPAD];        // packed symmetric weights, bf16
__device__ uchar2        g_jk[PPAD];              // pair -> (j,k)
__device__ float         g_inp[TLEN * HDIM * BSZ];// input projection, layout [t][h][b]
__device__ float         g_x [HDIM * BSZ];        // x, layout [h][b] (o = h*16+b)
__device__ __nv_bfloat16 g_r [HDIM * BSZ];        // tanh(x), bf16, [h][b]
__device__ float         g_part[NCTA * HDIM * BSZ]; // per-CTA partial rec [cta][o]
__device__ unsigned      g_barcnt;

// ---------------------------------------------------------------- helpers
__device__ __forceinline__ unsigned ld_acq(unsigned* p) {
    unsigned v;
    asm volatile("ld.acquire.gpu.u32 %0, [%1];" : "=r"(v) : "l"(p));
    return v;
}

__device__ __forceinline__ void gridbar(unsigned target) {
    __threadfence();
    __syncthreads();
    if (threadIdx.x == 0) {
        atomicAdd(&g_barcnt, 1u);
        while (ld_acq(&g_barcnt) < target * NCTA) { }
    }
    __syncthreads();
}

__device__ __forceinline__ void mma_bf16(float c[4],
        unsigned a0, unsigned a1, unsigned a2, unsigned a3,
        unsigned b0, unsigned b1) {
    asm volatile(
        "mma.sync.aligned.m16n8k16.row.col.f32.bf16.bf16.f32 "
        "{%0,%1,%2,%3}, {%4,%5,%6,%7}, {%8,%9}, {%0,%1,%2,%3};\n"
        : "+f"(c[0]), "+f"(c[1]), "+f"(c[2]), "+f"(c[3])
        : "r"(a0), "r"(a1), "r"(a2), "r"(a3), "r"(b0), "r"(b1));
}

// ---------------------------------------------------------------- prep kernels
__global__ void k_init(const float* __restrict__ x0) {
    int o = blockIdx.x * blockDim.x + threadIdx.x;
    if (o < HDIM * BSZ) {
        int h = o >> 4, b = o & 15;
        float v = x0[b * HDIM + h];
        g_x[o] = v;
        g_r[o] = __float2bfloat16(tanhf(v));
    }
    if (o == 0) g_barcnt = 0u;
}

__global__ void k_jk() {
    int p = blockIdx.x * blockDim.x + threadIdx.x;
    if (p >= PPAD) return;
    if (p >= NPAIR) { g_jk[p] = make_uchar2(0, 0); return; }
    double H2 = 2.0 * HDIM + 1.0;
    int j = (int)((H2 - sqrt(H2 * H2 - 8.0 * (double)p)) * 0.5);
    if (j < 0) j = 0;
    if (j > HDIM - 1) j = HDIM - 1;
    while (j + 1 <= HDIM - 1 && OFFJ(j + 1) <= p) j++;
    while (j > 0 && OFFJ(j) > p) j--;
    int k = j + (p - OFFJ(j));
    g_jk[p] = make_uchar2((unsigned char)j, (unsigned char)k);
}

__global__ void k_ws(const float* __restrict__ w_hh) {
    int p = blockIdx.y * blockDim.x + threadIdx.x;
    int i = blockIdx.x;
    if (p >= PPAD) return;
    float v = 0.f;
    if (p < NPAIR) {
        uchar2 jk = g_jk[p];
        int j = jk.x, k = jk.y;
        if (j == k) v = w_hh[(i * HDIM + j) * HDIM + j];
        else        v = w_hh[(i * HDIM + j) * HDIM + k] + w_hh[(i * HDIM + k) * HDIM + j];
    }
    g_ws[i * PPAD + p] = __float2bfloat16(v);
}

__global__ void k_inp(const float* __restrict__ u,
                      const float* __restrict__ w_in_w,
                      const float* __restrict__ w_in_b) {
    int idx = blockIdx.x * blockDim.x + threadIdx.x;
    if (idx >= TLEN * HDIM * BSZ) return;
    int t = idx / (HDIM * BSZ);
    int r = idx - t * (HDIM * BSZ);
    int h = r >> 4, b = r & 15;
    const float* up = u + (b * TLEN + t) * IDIM;
    float acc = w_in_b[h];
#pragma unroll
    for (int i = 0; i < IDIM; i++) acc += up[i] * w_in_w[h * IDIM + i];
    g_inp[idx] = acc;
}

// ---------------------------------------------------------------- main persistent kernel
#define SMEM_A   0
#define SMEM_P   (256 * ASTRIDE * 2)                 // 118784
#define SMEM_R   (SMEM_P + 16 * PSTRIDE * 2)         // 126208
#define SMEM_JK  (SMEM_R + HDIM * BSZ * 2)           // 134400
#define SMEM_TOT (SMEM_JK + KSLICE * 2)              // 134848

extern __shared__ char smem_raw[];

__global__ void __launch_bounds__(256, 1)
k_main(const float* __restrict__ noise, float* __restrict__ traj, float* __restrict__ xlast) {
    __nv_bfloat16* A_s = (__nv_bfloat16*)(smem_raw + SMEM_A);   // [256][ASTRIDE]
    __nv_bfloat16* P_s = (__nv_bfloat16*)(smem_raw + SMEM_P);   // [16][PSTRIDE]
    __nv_bfloat16* r_s = (__nv_bfloat16*)(smem_raw + SMEM_R);   // [h][b]
    uchar2*        jk_s = (uchar2*)(smem_raw + SMEM_JK);        // [KSLICE]

    const int tid  = threadIdx.x;
    const int cta  = blockIdx.x;
    const int lane = tid & 31;
    const int warp = tid >> 5;
    const int g    = lane >> 2;     // groupID
    const int tq   = lane & 3;      // threadID_in_group

    // Load this CTA's A slice (packed symmetric weights) into SMEM — once.
    const int c0 = cta * KSLICE;
    for (int idx = tid; idx < 256 * KSLICE; idx += 256) {
        int i = idx / KSLICE, kk = idx - i * KSLICE;
        A_s[i * ASTRIDE + kk] = g_ws[i * PPAD + c0 + kk];
    }
    for (int idx = tid; idx < KSLICE; idx += 256) jk_s[idx] = g_jk[c0 + idx];
    __syncthreads();

    const unsigned* As32 = (const unsigned*)A_s;   // stride 116 words per row
    const unsigned* Ps32 = (const unsigned*)P_s;

    // x lives in a register for the thread that owns output o (stable mapping)
    const int o_own = cta * 32 + lane;             // valid when cta<128 && warp==0
    float xreg = 0.f;
    if (cta < 128 && warp == 0) xreg = g_x[o_own];

    unsigned bar = 0;

    for (int t = 0; t < TLEN; t++) {
        // ---- load current r (bf16 [h][b]) into SMEM, bypass L1 (stale-L1 hazard)
        {
            const uint4* src = (const uint4*)g_r;   // 512 x uint4
            uint4* dst = (uint4*)r_s;
            for (int i2 = tid; i2 < 512; i2 += 256) dst[i2] = __ldcg(src + i2);
        }
        __syncthreads();

        // ---- build outer-product B tile: P_s[b][p] = r[b,j(p)] * r[b,k(p)]
        if (tid < KSLICE) {
            uchar2 jk = jk_s[tid];
            const __nv_bfloat16* rj = r_s + ((int)jk.x) * BSZ;
            const __nv_bfloat16* rk = r_s + ((int)jk.y) * BSZ;
#pragma unroll
            for (int n = 0; n < BSZ; n++) {
                float v = __bfloat162float(rj[n]) * __bfloat162float(rk[n]);
                P_s[n * PSTRIDE + tid] = __float2bfloat16(v);
            }
        }
        __syncthreads();

        // ---- MMA: D[256x16] += A[256 x KSLICE] * P[KSLICE x 16]
        float acc[2][2][4];
#pragma unroll
        for (int m2 = 0; m2 < 2; m2++)
#pragma unroll
            for (int nt = 0; nt < 2; nt++)
#pragma unroll
                for (int q = 0; q < 4; q++) acc[m2][nt][q] = 0.f;

#pragma unroll 2
        for (int kt = 0; kt < KSLICE / 16; kt++) {
            const int kw = kt * 8 + tq;   // word column base
            unsigned b0[2], b1[2];
#pragma unroll
            for (int nt = 0; nt < 2; nt++) {
                int n = nt * 8 + g;
                b0[nt] = Ps32[n * (PSTRIDE / 2) + kw];
                b1[nt] = Ps32[n * (PSTRIDE / 2) + kw + 4];
            }
#pragma unroll
            for (int m2 = 0; m2 < 2; m2++) {
                int mrow = (warp * 2 + m2) * 16 + g;
                unsigned a0 = As32[mrow       * (ASTRIDE / 2) + kw];
                unsigned a1 = As32[(mrow + 8) * (ASTRIDE / 2) + kw];
                unsigned a2 = As32[mrow       * (ASTRIDE / 2) + kw + 4];
                unsigned a3 = As32[(mrow + 8) * (ASTRIDE / 2) + kw + 4];
#pragma unroll
                for (int nt = 0; nt < 2; nt++)
                    mma_bf16(acc[m2][nt], a0, a1, a2, a3, b0[nt], b1[nt]);
            }
        }

        // ---- write partial rec for this CTA (coalesced, o = i*16 + b)
        {
            float* pc = g_part + cta * (HDIM * BSZ);
#pragma unroll
            for (int m2 = 0; m2 < 2; m2++) {
                int ibase = (warp * 2 + m2) * 16 + g;
#pragma unroll
                for (int nt = 0; nt < 2; nt++) {
                    int bb = nt * 8 + tq * 2;
                    *(float2*)(pc + ibase * 16 + bb)       = make_float2(acc[m2][nt][0], acc[m2][nt][1]);
                    *(float2*)(pc + (ibase + 8) * 16 + bb) = make_float2(acc[m2][nt][2], acc[m2][nt][3]);
                }
            }
        }

        bar++; gridbar(bar);

        // ---- phase B: reduce partials, Euler update, write next r + traj
        if (cta < 128 && warp == 0) {
            const int o = o_own;
            float s0 = 0.f, s1 = 0.f, s2 = 0.f, s3 = 0.f;
            const float* pp = g_part + o;
#pragma unroll
            for (int c = 0; c < NCTA; c += 4) {
                s0 += __ldcg(pp + (c + 0) * (HDIM * BSZ));
                s1 += __ldcg(pp + (c + 1) * (HDIM * BSZ));
                s2 += __ldcg(pp + (c + 2) * (HDIM * BSZ));
                s3 += __ldcg(pp + (c + 3) * (HDIM * BSZ));
            }
            float rec = (s0 + s1) + (s2 + s3);
            int h = o >> 4, b = o & 15;
            float np  = noise[t * (BSZ * HDIM) + b * HDIM + h];
            float inp = g_inp[t * (HDIM * BSZ) + o];
            float xn  = xreg + NOISE_STD * np + TAUC * (-xreg + rec + inp);
            xreg = xn;
            g_r[o] = __float2bfloat16(tanhf(xn));
            traj[b * (TLEN * HDIM) + t * HDIM + h] = xn;
            if (t == TLEN - 1) xlast[b * HDIM + h] = xn;
        }

        bar++; gridbar(bar);
    }
}

// ---------------------------------------------------------------- output projection
__global__ void k_out(const float* __restrict__ w_out_w,
                      const float* __restrict__ w_out_b,
                      const float* __restrict__ traj,
                      float* __restrict__ outp) {
    __shared__ float s_t[HDIM];
    int bt = blockIdx.x;                 // b*TLEN + t
    int tid = threadIdx.x;
    s_t[tid] = tanhf(traj[bt * HDIM + tid]);
    __syncthreads();
    int warp = tid >> 5, lane = tid & 31;
    float acc = 0.f;
#pragma unroll
    for (int q = 0; q < 8; q++)
        acc += s_t[lane + q * 32] * w_out_w[warp * HDIM + lane + q * 32];
#pragma unroll
    for (int off = 16; off; off >>= 1)
        acc += __shfl_xor_sync(0xffffffffu, acc, off);
    if (lane == 0) outp[bt * IDIM + warp] = acc + w_out_b[warp];
}

// ---------------------------------------------------------------- launch
extern "C" void kernel_launch(void* const* d_in, const int* in_sizes, int n_in,
                              void* d_out, int out_size) {
    const float* u       = (const float*)d_in[0];
    const float* x0      = (const float*)d_in[1];
    const float* noise   = (const float*)d_in[2];
    const float* w_hh    = (const float*)d_in[3];
    const float* w_in_w  = (const float*)d_in[4];
    const float* w_in_b  = (const float*)d_in[5];
    const float* w_out_w = (const float*)d_in[6];
    const float* w_out_b = (const float*)d_in[7];

    float* outp  = (float*)d_out;                       // [B,T,I]
    float* xlast = outp + BSZ * TLEN * IDIM;            // [B,H]
    float* traj  = xlast + BSZ * HDIM;                  // [B,T,H]

    cudaFuncSetAttribute(k_main, cudaFuncAttributeMaxDynamicSharedMemorySize, SMEM_TOT);

    k_init<<<(HDIM * BSZ + 255) / 256, 256>>>(x0);
    k_jk<<<(PPAD + 255) / 256, 256>>>();
    dim3 gw(256, (PPAD + 255) / 256);
    k_ws<<<gw, 256>>>(w_hh);
    k_inp<<<(TLEN * HDIM * BSZ + 255) / 256, 256>>>(u, w_in_w, w_in_b);
    k_main<<<NCTA, 256, SMEM_TOT>>>(noise, traj, xlast);
    k_out<<<BSZ * TLEN, 256>>>(w_out_w, w_out_b, traj, outp);
}

// round 3
// speedup vs baseline: 1.1028x; 1.1028x over previous
#include <cuda_runtime.h>
#include <cuda_bf16.h>
#include <math.h>

// Problem constants
#define BSZ   16
#define TLEN  512
#define IDIM  8
#define HDIM  256
#define NPAIR 32896              // H*(H+1)/2
#define KSLICE 224               // pairs per CTA (mult of 16)
#define NCTA  148
#define PPAD  (NCTA*KSLICE)      // 33152 padded pairs
#define ASTRIDE 232              // bf16 elems per A row (116 words -> conflict-free)
#define PSTRIDE 232
#define NOISE_STD 0.05f
#define TAUC 0.2f

#define OFFJ(j) ((j)*HDIM - ((j)*((j)-1))/2)

// Scratch (static device globals: no allocation allowed)
__device__ __nv_bfloat16 g_ws[256 * PPAD];        // packed symmetric weights, bf16
__device__ uchar2        g_jk[PPAD];              // pair -> (j,k)
__device__ float         g_c  [TLEN * HDIM * BSZ];// NOISE_STD*noise + TAU*inp, layout [t][o]
__device__ float         g_x [HDIM * BSZ];        // x, layout [h][b] (o = h*16+b)
__device__ __nv_bfloat16 g_r [HDIM * BSZ];        // tanh(x), bf16, [h][b]
__device__ float         g_part[NCTA * HDIM * BSZ]; // per-CTA partial rec [cta][o]
__device__ unsigned      g_barcnt;

// ---------------------------------------------------------------- helpers
__device__ __forceinline__ unsigned ld_acq(unsigned* p) {
    unsigned v;
    asm volatile("ld.acquire.gpu.u32 %0, [%1];" : "=r"(v) : "l"(p));
    return v;
}

__device__ __forceinline__ void gridbar(unsigned target) {
    __threadfence();
    __syncthreads();
    if (threadIdx.x == 0) {
        atomicAdd(&g_barcnt, 1u);
        while (ld_acq(&g_barcnt) < target * NCTA) { }
    }
    __syncthreads();
}

__device__ __forceinline__ void mma_bf16(float c[4],
        unsigned a0, unsigned a1, unsigned a2, unsigned a3,
        unsigned b0, unsigned b1) {
    asm volatile(
        "mma.sync.aligned.m16n8k16.row.col.f32.bf16.bf16.f32 "
        "{%0,%1,%2,%3}, {%4,%5,%6,%7}, {%8,%9}, {%0,%1,%2,%3};\n"
        : "+f"(c[0]), "+f"(c[1]), "+f"(c[2]), "+f"(c[3])
        : "r"(a0), "r"(a1), "r"(a2), "r"(a3), "r"(b0), "r"(b1));
}

// ---------------------------------------------------------------- prep kernels
__global__ void k_init(const float* __restrict__ x0) {
    int o = blockIdx.x * blockDim.x + threadIdx.x;
    if (o < HDIM * BSZ) {
        int h = o >> 4, b = o & 15;
        float v = x0[b * HDIM + h];
        g_x[o] = v;
        g_r[o] = __float2bfloat16(tanhf(v));
    }
    if (o == 0) g_barcnt = 0u;
}

__global__ void k_jk() {
    int p = blockIdx.x * blockDim.x + threadIdx.x;
    if (p >= PPAD) return;
    if (p >= NPAIR) { g_jk[p] = make_uchar2(0, 0); return; }
    double H2 = 2.0 * HDIM + 1.0;
    int j = (int)((H2 - sqrt(H2 * H2 - 8.0 * (double)p)) * 0.5);
    if (j < 0) j = 0;
    if (j > HDIM - 1) j = HDIM - 1;
    while (j + 1 <= HDIM - 1 && OFFJ(j + 1) <= p) j++;
    while (j > 0 && OFFJ(j) > p) j--;
    int k = j + (p - OFFJ(j));
    g_jk[p] = make_uchar2((unsigned char)j, (unsigned char)k);
}

__global__ void k_ws(const float* __restrict__ w_hh) {
    int p = blockIdx.y * blockDim.x + threadIdx.x;
    int i = blockIdx.x;
    if (p >= PPAD) return;
    float v = 0.f;
    if (p < NPAIR) {
        uchar2 jk = g_jk[p];
        int j = jk.x, k = jk.y;
        if (j == k) v = w_hh[(i * HDIM + j) * HDIM + j];
        else        v = w_hh[(i * HDIM + j) * HDIM + k] + w_hh[(i * HDIM + k) * HDIM + j];
    }
    g_ws[i * PPAD + p] = __float2bfloat16(v);
}

// c[t][o] = NOISE_STD * noise[t,b,h] + TAU * (u @ w_in + b_in)[t,b,h]
__global__ void k_pre(const float* __restrict__ u,
                      const float* __restrict__ w_in_w,
                      const float* __restrict__ w_in_b,
                      const float* __restrict__ noise) {
    int idx = blockIdx.x * blockDim.x + threadIdx.x;
    if (idx >= TLEN * HDIM * BSZ) return;
    int t = idx / (HDIM * BSZ);
    int r = idx - t * (HDIM * BSZ);
    int h = r >> 4, b = r & 15;
    const float* up = u + (b * TLEN + t) * IDIM;
    float acc = w_in_b[h];
#pragma unroll
    for (int i = 0; i < IDIM; i++) acc += up[i] * w_in_w[h * IDIM + i];
    float n = noise[t * (BSZ * HDIM) + b * HDIM + h];
    g_c[idx] = NOISE_STD * n + TAUC * acc;
}

// ---------------------------------------------------------------- main persistent kernel
#define SMEM_A   0
#define SMEM_P   (256 * ASTRIDE * 2)                 // 118784
#define SMEM_R   (SMEM_P + 16 * PSTRIDE * 2)         // 126208
#define SMEM_JK  (SMEM_R + HDIM * BSZ * 2)           // 134400
#define SMEM_RED (SMEM_JK + KSLICE * 2)              // 134848
#define SMEM_TOT (SMEM_RED + 8 * 32 * 4)             // 135872

extern __shared__ char smem_raw[];

__global__ void __launch_bounds__(256, 1)
k_main(float* __restrict__ traj, float* __restrict__ xlast) {
    __nv_bfloat16* A_s = (__nv_bfloat16*)(smem_raw + SMEM_A);   // [256][ASTRIDE]
    __nv_bfloat16* P_s = (__nv_bfloat16*)(smem_raw + SMEM_P);   // [16][PSTRIDE]
    __nv_bfloat16* r_s = (__nv_bfloat16*)(smem_raw + SMEM_R);   // [h][b]
    uchar2*        jk_s = (uchar2*)(smem_raw + SMEM_JK);        // [KSLICE]
    float*         red_s = (float*)(smem_raw + SMEM_RED);       // [8][32]

    const int tid  = threadIdx.x;
    const int cta  = blockIdx.x;
    const int lane = tid & 31;
    const int warp = tid >> 5;
    const int g    = lane >> 2;     // groupID
    const int tq   = lane & 3;      // threadID_in_group

    // Load this CTA's A slice (packed symmetric weights) into SMEM — once.
    const int c0 = cta * KSLICE;
    for (int idx = tid; idx < 256 * KSLICE; idx += 256) {
        int i = idx / KSLICE, kk = idx - i * KSLICE;
        A_s[i * ASTRIDE + kk] = g_ws[i * PPAD + c0 + kk];
    }
    for (int idx = tid; idx < KSLICE; idx += 256) jk_s[idx] = g_jk[c0 + idx];
    __syncthreads();

    const unsigned* As32 = (const unsigned*)A_s;   // stride 116 words per row
    const unsigned* Ps32 = (const unsigned*)P_s;

    // x lives in a register for the thread that owns output o (stable mapping)
    const bool owner = (cta < 128);
    const int o_own = cta * 32 + lane;             // valid when owner && warp==0
    float xreg = 0.f;
    if (owner && warp == 0) xreg = g_x[o_own];

    unsigned bar = 0;

    for (int t = 0; t < TLEN; t++) {
        // ---- prefetch the per-step drive term early (hides DRAM latency behind MMA)
        float cpre = 0.f;
        if (owner && warp == 0) cpre = g_c[t * (HDIM * BSZ) + o_own];

        // ---- load current r (bf16 [h][b]) into SMEM, bypass L1 (stale-L1 hazard)
        {
            const uint4* src = (const uint4*)g_r;   // 512 x uint4
            uint4* dst = (uint4*)r_s;
            for (int i2 = tid; i2 < 512; i2 += 256) dst[i2] = __ldcg(src + i2);
        }
        __syncthreads();

        // ---- build outer-product B tile: P_s[b][p] = r[b,j(p)] * r[b,k(p)]
        if (tid < KSLICE) {
            uchar2 jk = jk_s[tid];
            const __nv_bfloat16* rj = r_s + ((int)jk.x) * BSZ;
            const __nv_bfloat16* rk = r_s + ((int)jk.y) * BSZ;
#pragma unroll
            for (int n = 0; n < BSZ; n++) {
                float v = __bfloat162float(rj[n]) * __bfloat162float(rk[n]);
                P_s[n * PSTRIDE + tid] = __float2bfloat16(v);
            }
        }
        __syncthreads();

        // ---- MMA: D[256x16] += A[256 x KSLICE] * P[KSLICE x 16]
        float acc[2][2][4];
#pragma unroll
        for (int m2 = 0; m2 < 2; m2++)
#pragma unroll
            for (int nt = 0; nt < 2; nt++)
#pragma unroll
                for (int q = 0; q < 4; q++) acc[m2][nt][q] = 0.f;

#pragma unroll 2
        for (int kt = 0; kt < KSLICE / 16; kt++) {
            const int kw = kt * 8 + tq;   // word column base
            unsigned b0[2], b1[2];
#pragma unroll
            for (int nt = 0; nt < 2; nt++) {
                int n = nt * 8 + g;
                b0[nt] = Ps32[n * (PSTRIDE / 2) + kw];
                b1[nt] = Ps32[n * (PSTRIDE / 2) + kw + 4];
            }
#pragma unroll
            for (int m2 = 0; m2 < 2; m2++) {
                int mrow = (warp * 2 + m2) * 16 + g;
                unsigned a0 = As32[mrow       * (ASTRIDE / 2) + kw];
                unsigned a1 = As32[(mrow + 8) * (ASTRIDE / 2) + kw];
                unsigned a2 = As32[mrow       * (ASTRIDE / 2) + kw + 4];
                unsigned a3 = As32[(mrow + 8) * (ASTRIDE / 2) + kw + 4];
#pragma unroll
                for (int nt = 0; nt < 2; nt++)
                    mma_bf16(acc[m2][nt], a0, a1, a2, a3, b0[nt], b1[nt]);
            }
        }

        // ---- write partial rec for this CTA (coalesced, o = i*16 + b)
        {
            float* pc = g_part + cta * (HDIM * BSZ);
#pragma unroll
            for (int m2 = 0; m2 < 2; m2++) {
                int ibase = (warp * 2 + m2) * 16 + g;
#pragma unroll
                for (int nt = 0; nt < 2; nt++) {
                    int bb = nt * 8 + tq * 2;
                    *(float2*)(pc + ibase * 16 + bb)       = make_float2(acc[m2][nt][0], acc[m2][nt][1]);
                    *(float2*)(pc + (ibase + 8) * 16 + bb) = make_float2(acc[m2][nt][2], acc[m2][nt][3]);
                }
            }
        }

        bar++; gridbar(bar);

        // ---- phase B: parallel reduce across all 8 warps (coalesced, MLP~19)
        if (owner) {
            const int o_base = cta * 32;
            const float* pp = g_part + o_base + lane;
            float s0 = 0.f, s1 = 0.f;
#pragma unroll
            for (int it = 0; it < 19; it++) {
                int c = warp + it * 8;
                if (c < NCTA) {
                    float v = __ldcg(pp + c * (HDIM * BSZ));
                    if (it & 1) s1 += v; else s0 += v;
                }
            }
            red_s[warp * 32 + lane] = s0 + s1;
        }
        __syncthreads();

        if (owner && warp == 0) {
            float rec = 0.f;
#pragma unroll
            for (int w = 0; w < 8; w++) rec += red_s[w * 32 + lane];
            // x_new = (1-TAU)*x + TAU*rec + [NOISE_STD*n + TAU*inp]
            float xn = 0.8f * xreg + TAUC * rec + cpre;
            xreg = xn;
            g_r[o_own] = __float2bfloat16(tanhf(xn));
            int h = o_own >> 4, b = o_own & 15;
            traj[b * (TLEN * HDIM) + t * HDIM + h] = xn;
            if (t == TLEN - 1) xlast[b * HDIM + h] = xn;
        }

        if (t < TLEN - 1) { bar++; gridbar(bar); }
    }
}

// ---------------------------------------------------------------- output projection
__global__ void k_out(const float* __restrict__ w_out_w,
                      const float* __restrict__ w_out_b,
                      const float* __restrict__ traj,
                      float* __restrict__ outp) {
    __shared__ float s_t[HDIM];
    int bt = blockIdx.x;                 // b*TLEN + t
    int tid = threadIdx.x;
    s_t[tid] = tanhf(traj[bt * HDIM + tid]);
    __syncthreads();
    int warp = tid >> 5, lane = tid & 31;
    float acc = 0.f;
#pragma unroll
    for (int q = 0; q < 8; q++)
        acc += s_t[lane + q * 32] * w_out_w[warp * HDIM + lane + q * 32];
#pragma unroll
    for (int off = 16; off; off >>= 1)
        acc += __shfl_xor_sync(0xffffffffu, acc, off);
    if (lane == 0) outp[bt * IDIM + warp] = acc + w_out_b[warp];
}

// ---------------------------------------------------------------- launch
extern "C" void kernel_launch(void* const* d_in, const int* in_sizes, int n_in,
                              void* d_out, int out_size) {
    const float* u       = (const float*)d_in[0];
    const float* x0      = (const float*)d_in[1];
    const float* noise   = (const float*)d_in[2];
    const float* w_hh    = (const float*)d_in[3];
    const float* w_in_w  = (const float*)d_in[4];
    const float* w_in_b  = (const float*)d_in[5];
    const float* w_out_w = (const float*)d_in[6];
    const float* w_out_b = (const float*)d_in[7];

    float* outp  = (float*)d_out;                       // [B,T,I]
    float* xlast = outp + BSZ * TLEN * IDIM;            // [B,H]
    float* traj  = xlast + BSZ * HDIM;                  // [B,T,H]

    cudaFuncSetAttribute(k_main, cudaFuncAttributeMaxDynamicSharedMemorySize, SMEM_TOT);

    k_init<<<(HDIM * BSZ + 255) / 256, 256>>>(x0);
    k_jk<<<(PPAD + 255) / 256, 256>>>();
    dim3 gw(256, (PPAD + 255) / 256);
    k_ws<<<gw, 256>>>(w_hh);
    k_pre<<<(TLEN * HDIM * BSZ + 255) / 256, 256>>>(u, w_in_w, w_in_b, noise);
    k_main<<<NCTA, 256, SMEM_TOT>>>(traj, xlast);
    k_out<<<BSZ * TLEN, 256>>>(w_out_w, w_out_b, traj, outp);
}